// round 15
// baseline (speedup 1.0000x reference)
#include <cuda_runtime.h>
#include <cuda_fp16.h>
#include <cstdint>
#include <math.h>

#define Bn    8
#define NSPn  1024
#define Hn    256
#define Wn    256
#define Nn    (Bn*NSPn)      /* 8192 superpixel nodes */
#define NPIX  (Bn*Hn*Wn)     /* 524288 pixels */
#define En    131072         /* edges */

/* ------------------------- scratch (device globals) ------------------------ */
__device__ int    g_cnt[Nn];
__device__ int    g_off[Nn];
__device__ int    g_cur[Nn];
__device__ int    g_pix[NPIX];
__device__ float  g_pc[2*Nn];
__device__ int    g_ecnt[Nn];
__device__ int    g_eoff[Nn+1];
__device__ int    g_ecur[Nn];
__device__ int    g_esrc[En];
__device__ float  g_eew[En];
__device__ __half g_P0[8192*256];                /* projected skip0 @ 32x32, 4.2MB */
__device__ __half g_T0[(size_t)Bn*32*256*256];   /* 33.5 MB (projected, 256ch) */
__device__ __half g_T1[(size_t)Bn*64*256*256];   /* 67 MB  */
__device__ __half g_T2[(size_t)Bn*128*256*256];  /* 134 MB */
__device__ float  g_pool1[Nn*256];
__device__ float  g_pool2[Nn*256];
__device__ float  g_x[Nn*256];
__device__ float  g_h[Nn*256];
__device__ float  g_s[Nn];

/* ----- per-frame meta: hist + coord sums + scan (8 blocks, smem atomics) ---- */
__global__ __launch_bounds__(1024) void k_meta(const int* __restrict__ labels) {
    __shared__ int hist[1024];
    __shared__ int ssy[1024];
    __shared__ int ssx[1024];
    __shared__ int wsum[32];
    int b = blockIdx.x, tid = threadIdx.x;
    hist[tid] = 0; ssy[tid] = 0; ssx[tid] = 0;
    int gn = b*1024 + tid;
    g_ecnt[gn] = 0; g_ecur[gn] = 0;
    __syncthreads();
    const int* lb = labels + b*65536;
    for (int k = tid; k < 65536; k += 1024) {
        int l = lb[k];
        atomicAdd(&hist[l], 1);
        atomicAdd(&ssy[l], k >> 8);
        atomicAdd(&ssx[l], k & 255);
    }
    __syncthreads();
    int v = hist[tid];
    int lane = tid & 31, w = tid >> 5;
    int inc = v;
    #pragma unroll
    for (int d = 1; d < 32; d <<= 1) {
        int t = __shfl_up_sync(0xffffffffu, inc, d);
        if (lane >= d) inc += t;
    }
    if (lane == 31) wsum[w] = inc;
    __syncthreads();
    if (w == 0) {
        int s = wsum[lane];
        #pragma unroll
        for (int d = 1; d < 32; d <<= 1) {
            int t = __shfl_up_sync(0xffffffffu, s, d);
            if (lane >= d) s += t;
        }
        wsum[lane] = s;
    }
    __syncthreads();
    int excl = inc - v + (w ? wsum[w-1] : 0);
    int goff = b*65536 + excl;
    g_cnt[gn] = v;
    g_off[gn] = goff;
    g_cur[gn] = goff;
    float ic = 1.0f / (float)max(v, 1);
    g_pc[2*gn]   = (float)ssy[tid] * ic * (1.0f/255.0f);
    g_pc[2*gn+1] = (float)ssx[tid] * ic * (1.0f/255.0f);
}

/* full-chip counting-sort scatter */
__global__ void k_scatter(const int* __restrict__ labels) {
    int p = blockIdx.x*blockDim.x + threadIdx.x;
    if (p < NPIX) {
        int n = labels[p] + ((p >> 16) << 10);
        int pos = atomicAdd(&g_cur[n], 1);
        g_pix[pos] = p;
    }
}

/* edge weights + dst-degree count in one pass */
__global__ void k_ea(const int* __restrict__ edges, float* __restrict__ out_ea) {
    int e = blockIdx.x*blockDim.x + threadIdx.x;
    if (e < En) {
        int s = edges[e], d = edges[En + e];
        float dx = g_pc[2*s]   - g_pc[2*d];
        float dy = g_pc[2*s+1] - g_pc[2*d+1];
        out_ea[e] = expf(-(dx*dx + dy*dy) * 20.0f);   /* 1/SIGMA = 20 */
        atomicAdd(&g_ecnt[d], 1);
    }
}

/* exclusive scan of 8192 edge counts */
__global__ void k_escan() {
    __shared__ int part[1024];
    int tid = threadIdx.x;
    int base = tid * 8;
    int loc[8]; int s = 0;
    #pragma unroll
    for (int k = 0; k < 8; k++) { loc[k] = s; s += g_ecnt[base+k]; }
    part[tid] = s;
    __syncthreads();
    for (int d = 1; d < 1024; d <<= 1) {
        int v = (tid >= d) ? part[tid-d] : 0;
        __syncthreads();
        if (tid >= d) part[tid] += v;
        __syncthreads();
    }
    int pre = tid ? part[tid-1] : 0;
    #pragma unroll
    for (int k = 0; k < 8; k++) g_eoff[base+k] = pre + loc[k];
    if (tid == 1023) g_eoff[Nn] = part[1023];
}

__global__ void k_escatter(const int* __restrict__ edges, const float* __restrict__ ea) {
    int e = blockIdx.x*blockDim.x + threadIdx.x;
    if (e < En) {
        int d = edges[En + e];
        int pos = atomicAdd(&g_ecur[d], 1);
        int idx = g_eoff[d] + pos;
        g_esrc[idx] = edges[e];
        g_eew[idx]  = ea[e];
    }
}

__device__ __forceinline__ unsigned int f2tf32(float f) {
    unsigned int u;
    asm("cvt.rna.tf32.f32 %0, %1;" : "=r"(u) : "f"(f));
    return u;
}

/* ---- project skip0 @ W0 at 32x32 resolution: [8192 cells,512]@[512,256] ---- */
__global__ void k_proj0(const float* __restrict__ skip0, const float* __restrict__ Wm) {
    __shared__ float As[128][36];
    __shared__ float Bs[32][132];
    const int tid  = threadIdx.x;
    const int wid  = tid >> 5, lane = tid & 31;
    const int wm   = wid & 3, wn = wid >> 2;
    const int row_w = wm * 32;
    const int col_w = wn * 64;
    const int gid = lane >> 2, tig = lane & 3;
    const int mbase = blockIdx.x * 128;
    const int b = mbase >> 10;
    const int ijb = mbase & 1023;
    const int bn0 = blockIdx.y * 128;

    float acc[2][8][4];
    #pragma unroll
    for (int mt = 0; mt < 2; mt++)
        #pragma unroll
        for (int nt = 0; nt < 8; nt++)
            #pragma unroll
            for (int q = 0; q < 4; q++) acc[mt][nt][q] = 0.f;

    for (int k0 = 0; k0 < 512; k0 += 32) {
        #pragma unroll
        for (int i = 0; i < 4; i++) {
            int idx = tid + i*256;
            int kcol = idx >> 5, mseg = (idx & 31) * 4;
            float4 v = *(const float4*)(skip0 + ((size_t)(b*512 + k0 + kcol))*1024 + ijb + mseg);
            As[mseg  ][kcol] = __uint_as_float(f2tf32(v.x));
            As[mseg+1][kcol] = __uint_as_float(f2tf32(v.y));
            As[mseg+2][kcol] = __uint_as_float(f2tf32(v.z));
            As[mseg+3][kcol] = __uint_as_float(f2tf32(v.w));
        }
        #pragma unroll
        for (int i = 0; i < 4; i++) {
            int idx = tid + i*256;
            int kr = idx >> 5, c4 = (idx & 31) * 4;
            float4 v = *(const float4*)(Wm + (size_t)(k0+kr)*256 + bn0 + c4);
            Bs[kr][c4+0] = __uint_as_float(f2tf32(v.x));
            Bs[kr][c4+1] = __uint_as_float(f2tf32(v.y));
            Bs[kr][c4+2] = __uint_as_float(f2tf32(v.z));
            Bs[kr][c4+3] = __uint_as_float(f2tf32(v.w));
        }
        __syncthreads();
        #pragma unroll
        for (int kk = 0; kk < 32; kk += 8) {
            unsigned int af[2][4];
            #pragma unroll
            for (int mt = 0; mt < 2; mt++) {
                int r0 = row_w + mt*16 + gid;
                af[mt][0] = __float_as_uint(As[r0    ][kk + tig    ]);
                af[mt][1] = __float_as_uint(As[r0 + 8][kk + tig    ]);
                af[mt][2] = __float_as_uint(As[r0    ][kk + tig + 4]);
                af[mt][3] = __float_as_uint(As[r0 + 8][kk + tig + 4]);
            }
            #pragma unroll
            for (int nt = 0; nt < 8; nt++) {
                int n0 = col_w + nt*8 + gid;
                unsigned int b0 = __float_as_uint(Bs[kk + tig    ][n0]);
                unsigned int b1 = __float_as_uint(Bs[kk + tig + 4][n0]);
                #pragma unroll
                for (int mt = 0; mt < 2; mt++) {
                    asm volatile(
                        "mma.sync.aligned.m16n8k8.row.col.f32.tf32.tf32.f32 "
                        "{%0,%1,%2,%3}, {%4,%5,%6,%7}, {%8,%9}, {%0,%1,%2,%3};"
                        : "+f"(acc[mt][nt][0]), "+f"(acc[mt][nt][1]),
                          "+f"(acc[mt][nt][2]), "+f"(acc[mt][nt][3])
                        : "r"(af[mt][0]), "r"(af[mt][1]),
                          "r"(af[mt][2]), "r"(af[mt][3]),
                          "r"(b0), "r"(b1));
                }
            }
        }
        __syncthreads();
    }
    int grow = mbase + row_w;
    #pragma unroll
    for (int mt = 0; mt < 2; mt++) {
        #pragma unroll
        for (int nt = 0; nt < 8; nt++) {
            int r = grow + mt*16 + gid;
            int c = bn0 + col_w + nt*8 + tig*2;
            *(__half2*)(g_P0 + (size_t)r*256 + c) =
                __floats2half2_rn(acc[mt][nt][0], acc[mt][nt][1]);
            *(__half2*)(g_P0 + (size_t)(r+8)*256 + c) =
                __floats2half2_rn(acc[mt][nt][2], acc[mt][nt][3]);
        }
    }
}

/* W-expand projected skip0 (cell-major half input): block per (b,i) row ------ */
__global__ void k_tbuild0h() {
    __shared__ __half sm[32*256];
    int bi = blockIdx.x;          /* b*32 + i */
    int b = bi >> 5, i = bi & 31;
    const __half* src = g_P0 + (size_t)(b*1024 + i*32) * 256;
    const uint4* s4 = (const uint4*)src;
    uint4* d4 = (uint4*)sm;
    for (int t = threadIdx.x; t < 1024; t += blockDim.x) d4[t] = s4[t];
    __syncthreads();
    const float scale = 31.0f / 255.0f;
    __half* To = g_T0 + (size_t)bi * 65536;
    int x = threadIdx.x;
    float pos = (float)x * scale;
    int j0 = (int)pos;
    float wt = pos - (float)j0;
    int j1 = min(j0+1, 31);
    float w0 = 1.0f - wt;
    const __half2* r0 = (const __half2*)(sm + j0*256);
    const __half2* r1 = (const __half2*)(sm + j1*256);
    __half2* o2 = (__half2*)(To + (size_t)x*256);
    #pragma unroll 4
    for (int c2 = 0; c2 < 128; c2++) {
        float2 a = __half22float2(r0[c2]);
        float2 bb = __half22float2(r1[c2]);
        o2[c2] = __floats2half2_rn(w0*a.x + wt*bb.x, w0*a.y + wt*bb.y);
    }
}

/* -------------- half-separable upsample: expand W axis into T (half) ------- */
/* bi0 = starting (b*Hs + i) row offset, for per-frame pipelining.             */
template<int C, int Hs, int Ws, int CH>
__global__ void k_tbuild(const float* __restrict__ f, __half* __restrict__ T, int bi0) {
    __shared__ float sm[Ws*(CH+1)];
    constexpr int NCH = C / CH;
    int blk   = blockIdx.x;
    int chunk = blk % NCH;
    int bi    = bi0 + blk / NCH;        /* b*Hs + i */
    int b = bi / Hs, i = bi % Hs;
    int cbase = chunk * CH;
    const float* fb = f + ((size_t)(b*C + cbase)*Hs + i) * Ws;
    for (int t = threadIdx.x; t < CH*Ws; t += blockDim.x) {
        int c = t / Ws, j = t % Ws;
        sm[j*(CH+1) + c] = fb[(size_t)c*Hs*Ws + j];
    }
    __syncthreads();
    const float scale = (float)(Ws-1) / 255.0f;
    __half* To = T + (size_t)bi*256*C + cbase;
    for (int t = threadIdx.x; t < 256*(CH/2); t += blockDim.x) {
        int x = t / (CH/2), c = (t % (CH/2)) * 2;
        float pos = (float)x * scale;
        int j0 = (int)pos;
        float wt = pos - (float)j0;
        int j1 = min(j0+1, Ws-1);
        float w0 = 1.0f - wt;
        float v0 = sm[j0*(CH+1)+c  ]*w0 + sm[j1*(CH+1)+c  ]*wt;
        float v1 = sm[j0*(CH+1)+c+1]*w0 + sm[j1*(CH+1)+c+1]*wt;
        *(__half2*)(To + (size_t)x*C + c) = __floats2half2_rn(v0, v1);
    }
}

/* --------- superpixel pooling gather: warp per (node, 256-ch group) -------- */
/* n0/ncount select a node range (per-frame pipelining).                       */
template<int C, int Hs>
__global__ void k_gather(const __half* __restrict__ T, float* __restrict__ pool,
                         int n0, int ncount) {
    constexpr int G = C / 256;
    int gw = (blockIdx.x*blockDim.x + threadIdx.x) >> 5;
    if (gw >= ncount*G) return;
    int lane = threadIdx.x & 31;
    int n = n0 + gw / G, g = gw % G;
    int cb = g*256 + lane*8;
    int off = g_off[n], cnt = g_cnt[n];
    int b = n >> 10;
    const float scale = (float)(Hs-1) / 255.0f;
    float acc[8] = {};
    const __half* Tb = T + (size_t)b*Hs*256*C + cb;

    int k = 0;
    for (; k + 2 <= cnt; k += 2) {
        int p0 = g_pix[off + k];
        int p1 = g_pix[off + k + 1];
        int y0 = (p0 >> 8) & 255, x0 = p0 & 255;
        int y1 = (p1 >> 8) & 255, x1 = p1 & 255;
        float pos0 = (float)y0 * scale, pos1 = (float)y1 * scale;
        int i00 = (int)pos0, i10 = (int)pos1;
        float wt0 = pos0 - (float)i00, wt1 = pos1 - (float)i10;
        int i01 = min(i00+1, Hs-1), i11 = min(i10+1, Hs-1);
        uint4 a0 = *(const uint4*)(Tb + ((size_t)i00*256 + x0)*C);
        uint4 a1 = *(const uint4*)(Tb + ((size_t)i01*256 + x0)*C);
        uint4 c0 = *(const uint4*)(Tb + ((size_t)i10*256 + x1)*C);
        uint4 c1 = *(const uint4*)(Tb + ((size_t)i11*256 + x1)*C);
        float w00 = 1.0f - wt0, w10 = 1.0f - wt1;
        const __half2* ha0 = (const __half2*)&a0;
        const __half2* ha1 = (const __half2*)&a1;
        const __half2* hc0 = (const __half2*)&c0;
        const __half2* hc1 = (const __half2*)&c1;
        #pragma unroll
        for (int j = 0; j < 4; j++) {
            float2 fa0 = __half22float2(ha0[j]);
            float2 fa1 = __half22float2(ha1[j]);
            float2 fc0 = __half22float2(hc0[j]);
            float2 fc1 = __half22float2(hc1[j]);
            acc[2*j]   += w00*fa0.x + wt0*fa1.x + w10*fc0.x + wt1*fc1.x;
            acc[2*j+1] += w00*fa0.y + wt0*fa1.y + w10*fc0.y + wt1*fc1.y;
        }
    }
    if (k < cnt) {
        int p = g_pix[off + k];
        int y = (p >> 8) & 255, x = p & 255;
        float pos = (float)y * scale;
        int i0 = (int)pos;
        float wt = pos - (float)i0;
        int i1 = min(i0+1, Hs-1);
        float w0 = 1.0f - wt;
        uint4 u0 = *(const uint4*)(Tb + ((size_t)i0*256 + x)*C);
        uint4 u1 = *(const uint4*)(Tb + ((size_t)i1*256 + x)*C);
        const __half2* h0 = (const __half2*)&u0;
        const __half2* h1 = (const __half2*)&u1;
        #pragma unroll
        for (int j = 0; j < 4; j++) {
            float2 f0 = __half22float2(h0[j]);
            float2 f1 = __half22float2(h1[j]);
            acc[2*j]   += w0*f0.x + wt*f1.x;
            acc[2*j+1] += w0*f0.y + wt*f1.y;
        }
    }
    float inv = 1.0f / (float)max(cnt, 1);
    float4 r0 = make_float4(acc[0]*inv, acc[1]*inv, acc[2]*inv, acc[3]*inv);
    float4 r1 = make_float4(acc[4]*inv, acc[5]*inv, acc[6]*inv, acc[7]*inv);
    *(float4*)(pool + (size_t)n*C + cb)     = r0;
    *(float4*)(pool + (size_t)n*C + cb + 4) = r1;
}

/* ------------- TF32 tensor-core GEMM: [8192,256] @ [256,256] -> g_h --------- */
__global__ void k_gemm_tf32(const float* __restrict__ Wm) {
    constexpr int K = 256;
    __shared__ float As[128][36];
    __shared__ float Bs[32][132];
    const float* A = g_x;
    const int tid  = threadIdx.x;
    const int wid  = tid >> 5, lane = tid & 31;
    const int wm   = wid & 3, wn = wid >> 2;
    const int row_w = wm * 32;
    const int col_w = wn * 64;
    const int gid = lane >> 2, tig = lane & 3;
    const float* Ab = A + (size_t)blockIdx.x * 128 * K;
    const int bn0 = blockIdx.y * 128;

    float acc[2][8][4];
    #pragma unroll
    for (int mt = 0; mt < 2; mt++)
        #pragma unroll
        for (int nt = 0; nt < 8; nt++)
            #pragma unroll
            for (int q = 0; q < 4; q++) acc[mt][nt][q] = 0.f;

    for (int k0 = 0; k0 < K; k0 += 32) {
        #pragma unroll
        for (int i = 0; i < 4; i++) {
            int idx = tid + i*256;
            int r = idx >> 3, c4 = (idx & 7) * 4;
            float4 v = *(const float4*)(Ab + (size_t)r*K + k0 + c4);
            As[r][c4+0] = __uint_as_float(f2tf32(v.x));
            As[r][c4+1] = __uint_as_float(f2tf32(v.y));
            As[r][c4+2] = __uint_as_float(f2tf32(v.z));
            As[r][c4+3] = __uint_as_float(f2tf32(v.w));
        }
        #pragma unroll
        for (int i = 0; i < 4; i++) {
            int idx = tid + i*256;
            int kr = idx >> 5, c4 = (idx & 31) * 4;
            float4 v = *(const float4*)(Wm + (size_t)(k0+kr)*256 + bn0 + c4);
            Bs[kr][c4+0] = __uint_as_float(f2tf32(v.x));
            Bs[kr][c4+1] = __uint_as_float(f2tf32(v.y));
            Bs[kr][c4+2] = __uint_as_float(f2tf32(v.z));
            Bs[kr][c4+3] = __uint_as_float(f2tf32(v.w));
        }
        __syncthreads();
        #pragma unroll
        for (int kk = 0; kk < 32; kk += 8) {
            unsigned int af[2][4];
            #pragma unroll
            for (int mt = 0; mt < 2; mt++) {
                int r0 = row_w + mt*16 + gid;
                af[mt][0] = __float_as_uint(As[r0    ][kk + tig    ]);
                af[mt][1] = __float_as_uint(As[r0 + 8][kk + tig    ]);
                af[mt][2] = __float_as_uint(As[r0    ][kk + tig + 4]);
                af[mt][3] = __float_as_uint(As[r0 + 8][kk + tig + 4]);
            }
            #pragma unroll
            for (int nt = 0; nt < 8; nt++) {
                int n0 = col_w + nt*8 + gid;
                unsigned int b0 = __float_as_uint(Bs[kk + tig    ][n0]);
                unsigned int b1 = __float_as_uint(Bs[kk + tig + 4][n0]);
                #pragma unroll
                for (int mt = 0; mt < 2; mt++) {
                    asm volatile(
                        "mma.sync.aligned.m16n8k8.row.col.f32.tf32.tf32.f32 "
                        "{%0,%1,%2,%3}, {%4,%5,%6,%7}, {%8,%9}, {%0,%1,%2,%3};"
                        : "+f"(acc[mt][nt][0]), "+f"(acc[mt][nt][1]),
                          "+f"(acc[mt][nt][2]), "+f"(acc[mt][nt][3])
                        : "r"(af[mt][0]), "r"(af[mt][1]),
                          "r"(af[mt][2]), "r"(af[mt][3]),
                          "r"(b0), "r"(b1));
                }
            }
        }
        __syncthreads();
    }
    int grow = blockIdx.x*128 + row_w;
    #pragma unroll
    for (int mt = 0; mt < 2; mt++) {
        #pragma unroll
        for (int nt = 0; nt < 8; nt++) {
            int r = grow + mt*16 + gid;
            int c = bn0 + col_w + nt*8 + tig*2;
            *(float2*)(g_h + (size_t)r*256 + c) =
                make_float2(acc[mt][nt][0], acc[mt][nt][1]);
            *(float2*)(g_h + (size_t)(r+8)*256 + c) =
                make_float2(acc[mt][nt][2], acc[mt][nt][3]);
        }
    }
}

/* ----- GCN edge aggregation + bias + relu + skip mixing (+ final s dot) ---- */
__global__ void k_agg(const float* __restrict__ bias, int mixsel,
                      const float* __restrict__ lw) {
    int gw = (blockIdx.x*blockDim.x + threadIdx.x) >> 5;
    if (gw >= Nn) return;
    int lane = threadIdx.x & 31;
    int c0 = lane*4, c1 = c0 + 128;
    int off = g_eoff[gw], cnt = g_ecnt[gw];
    float4 A0 = make_float4(0,0,0,0), A1 = make_float4(0,0,0,0);
    for (int k = 0; k < cnt; k++) {
        int s = g_esrc[off + k];
        float w = g_eew[off + k];
        const float* hr = g_h + (size_t)s*256;
        float4 v0 = *(const float4*)(hr + c0);
        float4 v1 = *(const float4*)(hr + c1);
        A0.x += w*v0.x; A0.y += w*v0.y; A0.z += w*v0.z; A0.w += w*v0.w;
        A1.x += w*v1.x; A1.y += w*v1.y; A1.z += w*v1.z; A1.w += w*v1.w;
    }
    float4 b0 = *(const float4*)(bias + c0);
    float4 b1 = *(const float4*)(bias + c1);
    float4 r0 = make_float4(fmaxf(A0.x+b0.x,0.f), fmaxf(A0.y+b0.y,0.f),
                            fmaxf(A0.z+b0.z,0.f), fmaxf(A0.w+b0.w,0.f));
    float4 r1 = make_float4(fmaxf(A1.x+b1.x,0.f), fmaxf(A1.y+b1.y,0.f),
                            fmaxf(A1.z+b1.z,0.f), fmaxf(A1.w+b1.w,0.f));
    if (mixsel) {
        const float* pool = (mixsel == 1) ? g_pool1 : g_pool2;
        float4 p0 = *(const float4*)(pool + (size_t)gw*256 + c0);
        float4 p1 = *(const float4*)(pool + (size_t)gw*256 + c1);
        r0 = make_float4(0.5f*r0.x+0.5f*p0.x, 0.5f*r0.y+0.5f*p0.y,
                         0.5f*r0.z+0.5f*p0.z, 0.5f*r0.w+0.5f*p0.w);
        r1 = make_float4(0.5f*r1.x+0.5f*p1.x, 0.5f*r1.y+0.5f*p1.y,
                         0.5f*r1.z+0.5f*p1.z, 0.5f*r1.w+0.5f*p1.w);
        *(float4*)(g_x + (size_t)gw*256 + c0) = r0;
        *(float4*)(g_x + (size_t)gw*256 + c1) = r1;
    } else {
        float4 w0 = *(const float4*)(lw + c0);
        float4 w1 = *(const float4*)(lw + c1);
        float dot = r0.x*w0.x + r0.y*w0.y + r0.z*w0.z + r0.w*w0.w
                  + r1.x*w1.x + r1.y*w1.y + r1.z*w1.z + r1.w*w1.w;
        #pragma unroll
        for (int d = 16; d; d >>= 1) dot += __shfl_down_sync(0xffffffffu, dot, d);
        if (lane == 0) g_s[gw] = dot;
    }
}

__global__ void k_out(const int* __restrict__ edges, const int* __restrict__ negs,
                      float* __restrict__ out) {
    int e = blockIdx.x*blockDim.x + threadIdx.x;
    if (e < En) {
        float ss = g_s[edges[e]];
        float sd = g_s[edges[En + e]];
        float sn = g_s[negs[e]];
        out[e]      = 1.0f / (1.0f + expf(-(ss - sn)));   /* dan */
        out[En + e] = 1.0f / (1.0f + expf(-(ss - sd)));   /* dap */
    }
}

/* ------------------------------ launcher ----------------------------------- */
extern "C" void kernel_launch(void* const* d_in, const int* in_sizes, int n_in,
                              void* d_out, int out_size) {
    const int*   labels = (const int*)  d_in[0];
    const float* skip0  = (const float*)d_in[1];
    const float* skip1  = (const float*)d_in[2];
    const float* skip2  = (const float*)d_in[3];
    const int*   edges  = (const int*)  d_in[4];
    const int*   negs   = (const int*)  d_in[5];
    const float* W0     = (const float*)d_in[6];
    const float* b0     = (const float*)d_in[7];
    const float* W1     = (const float*)d_in[8];
    const float* b1     = (const float*)d_in[9];
    const float* W2     = (const float*)d_in[10];
    const float* b2     = (const float*)d_in[11];
    const float* lin_w  = (const float*)d_in[12];
    float* out = (float*)d_out;
    float* ea  = out + 2*En;

    static bool s_init = false;
    static cudaStream_t s1, s2, s3;
    static cudaEvent_t eStart, eSort, eG0, eG1, eG2;
    if (!s_init) {
        cudaStreamCreateWithFlags(&s1, cudaStreamNonBlocking);
        cudaStreamCreateWithFlags(&s2, cudaStreamNonBlocking);
        cudaStreamCreateWithFlags(&s3, cudaStreamNonBlocking);
        cudaEventCreateWithFlags(&eStart, cudaEventDisableTiming);
        cudaEventCreateWithFlags(&eSort,  cudaEventDisableTiming);
        cudaEventCreateWithFlags(&eG0,    cudaEventDisableTiming);
        cudaEventCreateWithFlags(&eG1,    cudaEventDisableTiming);
        cudaEventCreateWithFlags(&eG2,    cudaEventDisableTiming);
        s_init = true;
    }

    __half* T0 = nullptr; cudaGetSymbolAddress((void**)&T0, g_T0);
    __half* T1 = nullptr; cudaGetSymbolAddress((void**)&T1, g_T1);
    __half* T2 = nullptr; cudaGetSymbolAddress((void**)&T2, g_T2);
    float* p1 = nullptr; cudaGetSymbolAddress((void**)&p1, g_pool1);
    float* p2 = nullptr; cudaGetSymbolAddress((void**)&p2, g_pool2);
    float* ph = nullptr; cudaGetSymbolAddress((void**)&ph, g_h);

    /* fork side streams off the capture (default) stream */
    cudaEventRecord(eStart, 0);
    cudaStreamWaitEvent(s1, eStart, 0);
    cudaStreamWaitEvent(s2, eStart, 0);
    cudaStreamWaitEvent(s3, eStart, 0);

    /* s3: skip2 frame 0 tbuild early (overlaps sort); rest pipelined below.
       s1: proj0 + tbuild0; s2: skip1 tbuild. */
    k_tbuild<256, 128, 128, 64><<<128*4, 256, 0, s3>>>(skip2, T2, 0);
    k_proj0<<<dim3(64, 2), 256, 0, s1>>>(skip0, W0);
    k_tbuild0h<<<Bn*32, 256, 0, s1>>>();
    k_tbuild<256, 64, 64, 128><<<Bn*64*2, 256, 0, s2>>>(skip1, T1, 0);

    /* main stream: sort + CSR chain */
    k_meta<<<Bn, 1024>>>(labels);
    k_scatter<<<NPIX/256, 256>>>(labels);
    cudaEventRecord(eSort, 0);
    k_ea<<<En/256, 256>>>(edges, ea);
    k_escan<<<1, 1024>>>();
    k_escatter<<<En/256, 256>>>(edges, ea);

    /* s3: per-frame pipeline — tbuild2(b) then gather2(b) while the 16.8MB
       frame slice is L2-resident. Frame 0's tbuild already ran above. */
    cudaStreamWaitEvent(s3, eSort, 0);
    for (int b = 0; b < Bn; b++) {
        k_gather<256, 128><<<(1024*32)/256, 256, 0, s3>>>(T2, p2, b*1024, 1024);
        if (b + 1 < Bn)
            k_tbuild<256, 128, 128, 64><<<128*4, 256, 0, s3>>>(skip2, T2, (b+1)*128);
    }
    cudaEventRecord(eG2, s3);

    /* s1/s2: full-range gathers for T0 (L2-resident) and T1 */
    cudaStreamWaitEvent(s1, eSort, 0);
    k_gather<256, 32><<<(Nn*32)/256, 256, 0, s1>>>(T0, ph, 0, Nn);   /* pool(proj)=h0 */
    cudaEventRecord(eG0, s1);
    cudaStreamWaitEvent(s2, eSort, 0);
    k_gather<256, 64><<<(Nn*32)/256, 256, 0, s2>>>(T1, p1, 0, Nn);
    cudaEventRecord(eG1, s2);

    /* join: GCN chain on main stream */
    cudaStreamWaitEvent(0, eG0, 0);
    cudaStreamWaitEvent(0, eG1, 0);
    k_agg<<<Nn*32/256, 256>>>(b0, 1, lin_w);
    k_gemm_tf32<<<dim3(64, 2), 256>>>(W1);
    cudaStreamWaitEvent(0, eG2, 0);
    k_agg<<<Nn*32/256, 256>>>(b1, 2, lin_w);
    k_gemm_tf32<<<dim3(64, 2), 256>>>(W2);
    k_agg<<<Nn*32/256, 256>>>(b2, 0, lin_w);
    k_out<<<En/256, 256>>>(edges, negs, out);
}

// round 16
// speedup vs baseline: 1.0818x; 1.0818x over previous
#include <cuda_runtime.h>
#include <cuda_fp16.h>
#include <cstdint>
#include <math.h>

#define Bn    8
#define NSPn  1024
#define Hn    256
#define Wn    256
#define Nn    (Bn*NSPn)      /* 8192 superpixel nodes */
#define NPIX  (Bn*Hn*Wn)     /* 524288 pixels */
#define En    131072         /* edges */

/* ------------------------- scratch (device globals) ------------------------ */
__device__ int    g_cnt[Nn];
__device__ int    g_off[Nn];
__device__ int    g_cur[Nn];
__device__ int    g_pix[NPIX];
__device__ float  g_pc[2*Nn];
__device__ int    g_ecnt[Nn];
__device__ int    g_eoff[Nn+1];
__device__ int    g_ecur[Nn];
__device__ int    g_esrc[En];
__device__ float  g_eew[En];
__device__ __half g_P0[8192*256];                /* projected skip0 @ 32x32, 4.2MB */
__device__ __half g_T0[(size_t)Bn*32*256*256];   /* 33.5 MB (projected, 256ch) */
__device__ __half g_T1[(size_t)Bn*64*256*256];   /* 67 MB  */
__device__ __half g_T2[(size_t)Bn*128*256*256];  /* 134 MB */
__device__ float  g_pool1[Nn*256];
__device__ float  g_pool2[Nn*256];
__device__ float  g_x[Nn*256];
__device__ float  g_h[Nn*256];
__device__ float  g_s[Nn];

/* ----- per-frame meta: hist + coord sums + scan (8 blocks, smem atomics) ---- */
__global__ __launch_bounds__(1024) void k_meta(const int* __restrict__ labels) {
    __shared__ int hist[1024];
    __shared__ int ssy[1024];
    __shared__ int ssx[1024];
    __shared__ int wsum[32];
    int b = blockIdx.x, tid = threadIdx.x;
    hist[tid] = 0; ssy[tid] = 0; ssx[tid] = 0;
    int gn = b*1024 + tid;
    g_ecnt[gn] = 0; g_ecur[gn] = 0;
    __syncthreads();
    const int* lb = labels + b*65536;
    for (int k = tid; k < 65536; k += 1024) {
        int l = lb[k];
        atomicAdd(&hist[l], 1);
        atomicAdd(&ssy[l], k >> 8);
        atomicAdd(&ssx[l], k & 255);
    }
    __syncthreads();
    int v = hist[tid];
    int lane = tid & 31, w = tid >> 5;
    int inc = v;
    #pragma unroll
    for (int d = 1; d < 32; d <<= 1) {
        int t = __shfl_up_sync(0xffffffffu, inc, d);
        if (lane >= d) inc += t;
    }
    if (lane == 31) wsum[w] = inc;
    __syncthreads();
    if (w == 0) {
        int s = wsum[lane];
        #pragma unroll
        for (int d = 1; d < 32; d <<= 1) {
            int t = __shfl_up_sync(0xffffffffu, s, d);
            if (lane >= d) s += t;
        }
        wsum[lane] = s;
    }
    __syncthreads();
    int excl = inc - v + (w ? wsum[w-1] : 0);
    int goff = b*65536 + excl;
    g_cnt[gn] = v;
    g_off[gn] = goff;
    g_cur[gn] = goff;
    float ic = 1.0f / (float)max(v, 1);
    g_pc[2*gn]   = (float)ssy[tid] * ic * (1.0f/255.0f);
    g_pc[2*gn+1] = (float)ssx[tid] * ic * (1.0f/255.0f);
}

/* full-chip counting-sort scatter */
__global__ void k_scatter(const int* __restrict__ labels) {
    int p = blockIdx.x*blockDim.x + threadIdx.x;
    if (p < NPIX) {
        int n = labels[p] + ((p >> 16) << 10);
        int pos = atomicAdd(&g_cur[n], 1);
        g_pix[pos] = p;
    }
}

/* edge weights + dst-degree count in one pass */
__global__ void k_ea(const int* __restrict__ edges, float* __restrict__ out_ea) {
    int e = blockIdx.x*blockDim.x + threadIdx.x;
    if (e < En) {
        int s = edges[e], d = edges[En + e];
        float dx = g_pc[2*s]   - g_pc[2*d];
        float dy = g_pc[2*s+1] - g_pc[2*d+1];
        out_ea[e] = expf(-(dx*dx + dy*dy) * 20.0f);   /* 1/SIGMA = 20 */
        atomicAdd(&g_ecnt[d], 1);
    }
}

/* exclusive scan of 8192 edge counts */
__global__ void k_escan() {
    __shared__ int part[1024];
    int tid = threadIdx.x;
    int base = tid * 8;
    int loc[8]; int s = 0;
    #pragma unroll
    for (int k = 0; k < 8; k++) { loc[k] = s; s += g_ecnt[base+k]; }
    part[tid] = s;
    __syncthreads();
    for (int d = 1; d < 1024; d <<= 1) {
        int v = (tid >= d) ? part[tid-d] : 0;
        __syncthreads();
        if (tid >= d) part[tid] += v;
        __syncthreads();
    }
    int pre = tid ? part[tid-1] : 0;
    #pragma unroll
    for (int k = 0; k < 8; k++) g_eoff[base+k] = pre + loc[k];
    if (tid == 1023) g_eoff[Nn] = part[1023];
}

__global__ void k_escatter(const int* __restrict__ edges, const float* __restrict__ ea) {
    int e = blockIdx.x*blockDim.x + threadIdx.x;
    if (e < En) {
        int d = edges[En + e];
        int pos = atomicAdd(&g_ecur[d], 1);
        int idx = g_eoff[d] + pos;
        g_esrc[idx] = edges[e];
        g_eew[idx]  = ea[e];
    }
}

__device__ __forceinline__ unsigned int f2tf32(float f) {
    unsigned int u;
    asm("cvt.rna.tf32.f32 %0, %1;" : "=r"(u) : "f"(f));
    return u;
}

/* ---- project skip0 @ W0 at 32x32 resolution: [8192 cells,512]@[512,256] ---- */
__global__ void k_proj0(const float* __restrict__ skip0, const float* __restrict__ Wm) {
    __shared__ float As[128][36];
    __shared__ float Bs[32][132];
    const int tid  = threadIdx.x;
    const int wid  = tid >> 5, lane = tid & 31;
    const int wm   = wid & 3, wn = wid >> 2;
    const int row_w = wm * 32;
    const int col_w = wn * 64;
    const int gid = lane >> 2, tig = lane & 3;
    const int mbase = blockIdx.x * 128;
    const int b = mbase >> 10;
    const int ijb = mbase & 1023;
    const int bn0 = blockIdx.y * 128;

    float acc[2][8][4];
    #pragma unroll
    for (int mt = 0; mt < 2; mt++)
        #pragma unroll
        for (int nt = 0; nt < 8; nt++)
            #pragma unroll
            for (int q = 0; q < 4; q++) acc[mt][nt][q] = 0.f;

    for (int k0 = 0; k0 < 512; k0 += 32) {
        #pragma unroll
        for (int i = 0; i < 4; i++) {
            int idx = tid + i*256;
            int kcol = idx >> 5, mseg = (idx & 31) * 4;
            float4 v = *(const float4*)(skip0 + ((size_t)(b*512 + k0 + kcol))*1024 + ijb + mseg);
            As[mseg  ][kcol] = __uint_as_float(f2tf32(v.x));
            As[mseg+1][kcol] = __uint_as_float(f2tf32(v.y));
            As[mseg+2][kcol] = __uint_as_float(f2tf32(v.z));
            As[mseg+3][kcol] = __uint_as_float(f2tf32(v.w));
        }
        #pragma unroll
        for (int i = 0; i < 4; i++) {
            int idx = tid + i*256;
            int kr = idx >> 5, c4 = (idx & 31) * 4;
            float4 v = *(const float4*)(Wm + (size_t)(k0+kr)*256 + bn0 + c4);
            Bs[kr][c4+0] = __uint_as_float(f2tf32(v.x));
            Bs[kr][c4+1] = __uint_as_float(f2tf32(v.y));
            Bs[kr][c4+2] = __uint_as_float(f2tf32(v.z));
            Bs[kr][c4+3] = __uint_as_float(f2tf32(v.w));
        }
        __syncthreads();
        #pragma unroll
        for (int kk = 0; kk < 32; kk += 8) {
            unsigned int af[2][4];
            #pragma unroll
            for (int mt = 0; mt < 2; mt++) {
                int r0 = row_w + mt*16 + gid;
                af[mt][0] = __float_as_uint(As[r0    ][kk + tig    ]);
                af[mt][1] = __float_as_uint(As[r0 + 8][kk + tig    ]);
                af[mt][2] = __float_as_uint(As[r0    ][kk + tig + 4]);
                af[mt][3] = __float_as_uint(As[r0 + 8][kk + tig + 4]);
            }
            #pragma unroll
            for (int nt = 0; nt < 8; nt++) {
                int n0 = col_w + nt*8 + gid;
                unsigned int b0 = __float_as_uint(Bs[kk + tig    ][n0]);
                unsigned int b1 = __float_as_uint(Bs[kk + tig + 4][n0]);
                #pragma unroll
                for (int mt = 0; mt < 2; mt++) {
                    asm volatile(
                        "mma.sync.aligned.m16n8k8.row.col.f32.tf32.tf32.f32 "
                        "{%0,%1,%2,%3}, {%4,%5,%6,%7}, {%8,%9}, {%0,%1,%2,%3};"
                        : "+f"(acc[mt][nt][0]), "+f"(acc[mt][nt][1]),
                          "+f"(acc[mt][nt][2]), "+f"(acc[mt][nt][3])
                        : "r"(af[mt][0]), "r"(af[mt][1]),
                          "r"(af[mt][2]), "r"(af[mt][3]),
                          "r"(b0), "r"(b1));
                }
            }
        }
        __syncthreads();
    }
    int grow = mbase + row_w;
    #pragma unroll
    for (int mt = 0; mt < 2; mt++) {
        #pragma unroll
        for (int nt = 0; nt < 8; nt++) {
            int r = grow + mt*16 + gid;
            int c = bn0 + col_w + nt*8 + tig*2;
            *(__half2*)(g_P0 + (size_t)r*256 + c) =
                __floats2half2_rn(acc[mt][nt][0], acc[mt][nt][1]);
            *(__half2*)(g_P0 + (size_t)(r+8)*256 + c) =
                __floats2half2_rn(acc[mt][nt][2], acc[mt][nt][3]);
        }
    }
}

/* W-expand projected skip0 (cell-major half input): block per (b,i) row ------ */
__global__ void k_tbuild0h() {
    __shared__ __half sm[32*256];
    int bi = blockIdx.x;          /* b*32 + i */
    int b = bi >> 5, i = bi & 31;
    const __half* src = g_P0 + (size_t)(b*1024 + i*32) * 256;
    const uint4* s4 = (const uint4*)src;
    uint4* d4 = (uint4*)sm;
    for (int t = threadIdx.x; t < 1024; t += blockDim.x) d4[t] = s4[t];
    __syncthreads();
    const float scale = 31.0f / 255.0f;
    __half* To = g_T0 + (size_t)bi * 65536;
    int x = threadIdx.x;
    float pos = (float)x * scale;
    int j0 = (int)pos;
    float wt = pos - (float)j0;
    int j1 = min(j0+1, 31);
    float w0 = 1.0f - wt;
    const __half2* r0 = (const __half2*)(sm + j0*256);
    const __half2* r1 = (const __half2*)(sm + j1*256);
    __half2* o2 = (__half2*)(To + (size_t)x*256);
    #pragma unroll 4
    for (int c2 = 0; c2 < 128; c2++) {
        float2 a = __half22float2(r0[c2]);
        float2 bb = __half22float2(r1[c2]);
        o2[c2] = __floats2half2_rn(w0*a.x + wt*bb.x, w0*a.y + wt*bb.y);
    }
}

/* -------------- half-separable upsample: expand W axis into T (half) ------- */
template<int C, int Hs, int Ws, int CH>
__global__ void k_tbuild(const float* __restrict__ f, __half* __restrict__ T) {
    __shared__ float sm[Ws*(CH+1)];
    constexpr int NCH = C / CH;
    int blk   = blockIdx.x;
    int chunk = blk % NCH;
    int bi    = blk / NCH;              /* b*Hs + i */
    int b = bi / Hs, i = bi % Hs;
    int cbase = chunk * CH;
    const float* fb = f + ((size_t)(b*C + cbase)*Hs + i) * Ws;
    for (int t = threadIdx.x; t < CH*Ws; t += blockDim.x) {
        int c = t / Ws, j = t % Ws;
        sm[j*(CH+1) + c] = fb[(size_t)c*Hs*Ws + j];
    }
    __syncthreads();
    const float scale = (float)(Ws-1) / 255.0f;
    __half* To = T + (size_t)bi*256*C + cbase;
    for (int t = threadIdx.x; t < 256*(CH/2); t += blockDim.x) {
        int x = t / (CH/2), c = (t % (CH/2)) * 2;
        float pos = (float)x * scale;
        int j0 = (int)pos;
        float wt = pos - (float)j0;
        int j1 = min(j0+1, Ws-1);
        float w0 = 1.0f - wt;
        float v0 = sm[j0*(CH+1)+c  ]*w0 + sm[j1*(CH+1)+c  ]*wt;
        float v1 = sm[j0*(CH+1)+c+1]*w0 + sm[j1*(CH+1)+c+1]*wt;
        *(__half2*)(To + (size_t)x*C + c) = __floats2half2_rn(v0, v1);
    }
}

/* --- superpixel pooling gather: persistent grid-stride, warp per node ------ */
/* Bounded grid => all warps sweep nodes in lockstep order => the active T     */
/* window is ~1 frame slice and stays L2-resident (4x reuse).                  */
template<int C, int Hs>
__global__ void k_gather(const __half* __restrict__ T, float* __restrict__ pool) {
    constexpr int G = C / 256;
    int lane = threadIdx.x & 31;
    int gw0  = (blockIdx.x*blockDim.x + threadIdx.x) >> 5;
    int step = (gridDim.x*blockDim.x) >> 5;
    const float scale = (float)(Hs-1) / 255.0f;

    for (int gw = gw0; gw < Nn*G; gw += step) {
        int n = gw / G, g = gw % G;
        int cb = g*256 + lane*8;
        int off = g_off[n], cnt = g_cnt[n];
        int b = n >> 10;
        float acc[8] = {};
        const __half* Tb = T + (size_t)b*Hs*256*C + cb;

        int k = 0;
        for (; k + 2 <= cnt; k += 2) {
            int p0 = g_pix[off + k];
            int p1 = g_pix[off + k + 1];
            int y0 = (p0 >> 8) & 255, x0 = p0 & 255;
            int y1 = (p1 >> 8) & 255, x1 = p1 & 255;
            float pos0 = (float)y0 * scale, pos1 = (float)y1 * scale;
            int i00 = (int)pos0, i10 = (int)pos1;
            float wt0 = pos0 - (float)i00, wt1 = pos1 - (float)i10;
            int i01 = min(i00+1, Hs-1), i11 = min(i10+1, Hs-1);
            uint4 a0 = *(const uint4*)(Tb + ((size_t)i00*256 + x0)*C);
            uint4 a1 = *(const uint4*)(Tb + ((size_t)i01*256 + x0)*C);
            uint4 c0 = *(const uint4*)(Tb + ((size_t)i10*256 + x1)*C);
            uint4 c1 = *(const uint4*)(Tb + ((size_t)i11*256 + x1)*C);
            float w00 = 1.0f - wt0, w10 = 1.0f - wt1;
            const __half2* ha0 = (const __half2*)&a0;
            const __half2* ha1 = (const __half2*)&a1;
            const __half2* hc0 = (const __half2*)&c0;
            const __half2* hc1 = (const __half2*)&c1;
            #pragma unroll
            for (int j = 0; j < 4; j++) {
                float2 fa0 = __half22float2(ha0[j]);
                float2 fa1 = __half22float2(ha1[j]);
                float2 fc0 = __half22float2(hc0[j]);
                float2 fc1 = __half22float2(hc1[j]);
                acc[2*j]   += w00*fa0.x + wt0*fa1.x + w10*fc0.x + wt1*fc1.x;
                acc[2*j+1] += w00*fa0.y + wt0*fa1.y + w10*fc0.y + wt1*fc1.y;
            }
        }
        if (k < cnt) {
            int p = g_pix[off + k];
            int y = (p >> 8) & 255, x = p & 255;
            float pos = (float)y * scale;
            int i0 = (int)pos;
            float wt = pos - (float)i0;
            int i1 = min(i0+1, Hs-1);
            float w0 = 1.0f - wt;
            uint4 u0 = *(const uint4*)(Tb + ((size_t)i0*256 + x)*C);
            uint4 u1 = *(const uint4*)(Tb + ((size_t)i1*256 + x)*C);
            const __half2* h0 = (const __half2*)&u0;
            const __half2* h1 = (const __half2*)&u1;
            #pragma unroll
            for (int j = 0; j < 4; j++) {
                float2 f0 = __half22float2(h0[j]);
                float2 f1 = __half22float2(h1[j]);
                acc[2*j]   += w0*f0.x + wt*f1.x;
                acc[2*j+1] += w0*f0.y + wt*f1.y;
            }
        }
        float inv = 1.0f / (float)max(cnt, 1);
        float4 r0 = make_float4(acc[0]*inv, acc[1]*inv, acc[2]*inv, acc[3]*inv);
        float4 r1 = make_float4(acc[4]*inv, acc[5]*inv, acc[6]*inv, acc[7]*inv);
        *(float4*)(pool + (size_t)n*C + cb)     = r0;
        *(float4*)(pool + (size_t)n*C + cb + 4) = r1;
    }
}

/* ------------- TF32 tensor-core GEMM: [8192,256] @ [256,256] -> g_h --------- */
__global__ void k_gemm_tf32(const float* __restrict__ Wm) {
    constexpr int K = 256;
    __shared__ float As[128][36];
    __shared__ float Bs[32][132];
    const float* A = g_x;
    const int tid  = threadIdx.x;
    const int wid  = tid >> 5, lane = tid & 31;
    const int wm   = wid & 3, wn = wid >> 2;
    const int row_w = wm * 32;
    const int col_w = wn * 64;
    const int gid = lane >> 2, tig = lane & 3;
    const float* Ab = A + (size_t)blockIdx.x * 128 * K;
    const int bn0 = blockIdx.y * 128;

    float acc[2][8][4];
    #pragma unroll
    for (int mt = 0; mt < 2; mt++)
        #pragma unroll
        for (int nt = 0; nt < 8; nt++)
            #pragma unroll
            for (int q = 0; q < 4; q++) acc[mt][nt][q] = 0.f;

    for (int k0 = 0; k0 < K; k0 += 32) {
        #pragma unroll
        for (int i = 0; i < 4; i++) {
            int idx = tid + i*256;
            int r = idx >> 3, c4 = (idx & 7) * 4;
            float4 v = *(const float4*)(Ab + (size_t)r*K + k0 + c4);
            As[r][c4+0] = __uint_as_float(f2tf32(v.x));
            As[r][c4+1] = __uint_as_float(f2tf32(v.y));
            As[r][c4+2] = __uint_as_float(f2tf32(v.z));
            As[r][c4+3] = __uint_as_float(f2tf32(v.w));
        }
        #pragma unroll
        for (int i = 0; i < 4; i++) {
            int idx = tid + i*256;
            int kr = idx >> 5, c4 = (idx & 31) * 4;
            float4 v = *(const float4*)(Wm + (size_t)(k0+kr)*256 + bn0 + c4);
            Bs[kr][c4+0] = __uint_as_float(f2tf32(v.x));
            Bs[kr][c4+1] = __uint_as_float(f2tf32(v.y));
            Bs[kr][c4+2] = __uint_as_float(f2tf32(v.z));
            Bs[kr][c4+3] = __uint_as_float(f2tf32(v.w));
        }
        __syncthreads();
        #pragma unroll
        for (int kk = 0; kk < 32; kk += 8) {
            unsigned int af[2][4];
            #pragma unroll
            for (int mt = 0; mt < 2; mt++) {
                int r0 = row_w + mt*16 + gid;
                af[mt][0] = __float_as_uint(As[r0    ][kk + tig    ]);
                af[mt][1] = __float_as_uint(As[r0 + 8][kk + tig    ]);
                af[mt][2] = __float_as_uint(As[r0    ][kk + tig + 4]);
                af[mt][3] = __float_as_uint(As[r0 + 8][kk + tig + 4]);
            }
            #pragma unroll
            for (int nt = 0; nt < 8; nt++) {
                int n0 = col_w + nt*8 + gid;
                unsigned int b0 = __float_as_uint(Bs[kk + tig    ][n0]);
                unsigned int b1 = __float_as_uint(Bs[kk + tig + 4][n0]);
                #pragma unroll
                for (int mt = 0; mt < 2; mt++) {
                    asm volatile(
                        "mma.sync.aligned.m16n8k8.row.col.f32.tf32.tf32.f32 "
                        "{%0,%1,%2,%3}, {%4,%5,%6,%7}, {%8,%9}, {%0,%1,%2,%3};"
                        : "+f"(acc[mt][nt][0]), "+f"(acc[mt][nt][1]),
                          "+f"(acc[mt][nt][2]), "+f"(acc[mt][nt][3])
                        : "r"(af[mt][0]), "r"(af[mt][1]),
                          "r"(af[mt][2]), "r"(af[mt][3]),
                          "r"(b0), "r"(b1));
                }
            }
        }
        __syncthreads();
    }
    int grow = blockIdx.x*128 + row_w;
    #pragma unroll
    for (int mt = 0; mt < 2; mt++) {
        #pragma unroll
        for (int nt = 0; nt < 8; nt++) {
            int r = grow + mt*16 + gid;
            int c = bn0 + col_w + nt*8 + tig*2;
            *(float2*)(g_h + (size_t)r*256 + c) =
                make_float2(acc[mt][nt][0], acc[mt][nt][1]);
            *(float2*)(g_h + (size_t)(r+8)*256 + c) =
                make_float2(acc[mt][nt][2], acc[mt][nt][3]);
        }
    }
}

/* ----- GCN edge aggregation + bias + relu + skip mixing (+ final s dot) ---- */
__global__ void k_agg(const float* __restrict__ bias, int mixsel,
                      const float* __restrict__ lw) {
    int gw = (blockIdx.x*blockDim.x + threadIdx.x) >> 5;
    if (gw >= Nn) return;
    int lane = threadIdx.x & 31;
    int c0 = lane*4, c1 = c0 + 128;
    int off = g_eoff[gw], cnt = g_ecnt[gw];
    float4 A0 = make_float4(0,0,0,0), A1 = make_float4(0,0,0,0);
    for (int k = 0; k < cnt; k++) {
        int s = g_esrc[off + k];
        float w = g_eew[off + k];
        const float* hr = g_h + (size_t)s*256;
        float4 v0 = *(const float4*)(hr + c0);
        float4 v1 = *(const float4*)(hr + c1);
        A0.x += w*v0.x; A0.y += w*v0.y; A0.z += w*v0.z; A0.w += w*v0.w;
        A1.x += w*v1.x; A1.y += w*v1.y; A1.z += w*v1.z; A1.w += w*v1.w;
    }
    float4 b0 = *(const float4*)(bias + c0);
    float4 b1 = *(const float4*)(bias + c1);
    float4 r0 = make_float4(fmaxf(A0.x+b0.x,0.f), fmaxf(A0.y+b0.y,0.f),
                            fmaxf(A0.z+b0.z,0.f), fmaxf(A0.w+b0.w,0.f));
    float4 r1 = make_float4(fmaxf(A1.x+b1.x,0.f), fmaxf(A1.y+b1.y,0.f),
                            fmaxf(A1.z+b1.z,0.f), fmaxf(A1.w+b1.w,0.f));
    if (mixsel) {
        const float* pool = (mixsel == 1) ? g_pool1 : g_pool2;
        float4 p0 = *(const float4*)(pool + (size_t)gw*256 + c0);
        float4 p1 = *(const float4*)(pool + (size_t)gw*256 + c1);
        r0 = make_float4(0.5f*r0.x+0.5f*p0.x, 0.5f*r0.y+0.5f*p0.y,
                         0.5f*r0.z+0.5f*p0.z, 0.5f*r0.w+0.5f*p0.w);
        r1 = make_float4(0.5f*r1.x+0.5f*p1.x, 0.5f*r1.y+0.5f*p1.y,
                         0.5f*r1.z+0.5f*p1.z, 0.5f*r1.w+0.5f*p1.w);
        *(float4*)(g_x + (size_t)gw*256 + c0) = r0;
        *(float4*)(g_x + (size_t)gw*256 + c1) = r1;
    } else {
        float4 w0 = *(const float4*)(lw + c0);
        float4 w1 = *(const float4*)(lw + c1);
        float dot = r0.x*w0.x + r0.y*w0.y + r0.z*w0.z + r0.w*w0.w
                  + r1.x*w1.x + r1.y*w1.y + r1.z*w1.z + r1.w*w1.w;
        #pragma unroll
        for (int d = 16; d; d >>= 1) dot += __shfl_down_sync(0xffffffffu, dot, d);
        if (lane == 0) g_s[gw] = dot;
    }
}

__global__ void k_out(const int* __restrict__ edges, const int* __restrict__ negs,
                      float* __restrict__ out) {
    int e = blockIdx.x*blockDim.x + threadIdx.x;
    if (e < En) {
        float ss = g_s[edges[e]];
        float sd = g_s[edges[En + e]];
        float sn = g_s[negs[e]];
        out[e]      = 1.0f / (1.0f + expf(-(ss - sn)));   /* dan */
        out[En + e] = 1.0f / (1.0f + expf(-(ss - sd)));   /* dap */
    }
}

/* ------------------------------ launcher ----------------------------------- */
extern "C" void kernel_launch(void* const* d_in, const int* in_sizes, int n_in,
                              void* d_out, int out_size) {
    const int*   labels = (const int*)  d_in[0];
    const float* skip0  = (const float*)d_in[1];
    const float* skip1  = (const float*)d_in[2];
    const float* skip2  = (const float*)d_in[3];
    const int*   edges  = (const int*)  d_in[4];
    const int*   negs   = (const int*)  d_in[5];
    const float* W0     = (const float*)d_in[6];
    const float* b0     = (const float*)d_in[7];
    const float* W1     = (const float*)d_in[8];
    const float* b1     = (const float*)d_in[9];
    const float* W2     = (const float*)d_in[10];
    const float* b2     = (const float*)d_in[11];
    const float* lin_w  = (const float*)d_in[12];
    float* out = (float*)d_out;
    float* ea  = out + 2*En;

    static bool s_init = false;
    static cudaStream_t s1, s2, s3;
    static cudaEvent_t eStart, eSort, eG0, eG1, eG2;
    if (!s_init) {
        cudaStreamCreateWithFlags(&s1, cudaStreamNonBlocking);
        cudaStreamCreateWithFlags(&s2, cudaStreamNonBlocking);
        cudaStreamCreateWithFlags(&s3, cudaStreamNonBlocking);
        cudaEventCreateWithFlags(&eStart, cudaEventDisableTiming);
        cudaEventCreateWithFlags(&eSort,  cudaEventDisableTiming);
        cudaEventCreateWithFlags(&eG0,    cudaEventDisableTiming);
        cudaEventCreateWithFlags(&eG1,    cudaEventDisableTiming);
        cudaEventCreateWithFlags(&eG2,    cudaEventDisableTiming);
        s_init = true;
    }

    __half* T0 = nullptr; cudaGetSymbolAddress((void**)&T0, g_T0);
    __half* T1 = nullptr; cudaGetSymbolAddress((void**)&T1, g_T1);
    __half* T2 = nullptr; cudaGetSymbolAddress((void**)&T2, g_T2);
    float* p1 = nullptr; cudaGetSymbolAddress((void**)&p1, g_pool1);
    float* p2 = nullptr; cudaGetSymbolAddress((void**)&p2, g_pool2);
    float* ph = nullptr; cudaGetSymbolAddress((void**)&ph, g_h);

    /* fork side streams off the capture (default) stream */
    cudaEventRecord(eStart, 0);
    cudaStreamWaitEvent(s1, eStart, 0);
    cudaStreamWaitEvent(s2, eStart, 0);
    cudaStreamWaitEvent(s3, eStart, 0);

    /* s3: skip2 tbuild (critical path, launch first); s1: proj0; s2: skip1 */
    k_tbuild<256, 128, 128, 64><<<Bn*128*4, 256, 0, s3>>>(skip2, T2);
    k_proj0<<<dim3(64, 2), 256, 0, s1>>>(skip0, W0);
    k_tbuild0h<<<Bn*32, 256, 0, s1>>>();
    k_tbuild<256, 64, 64, 128><<<Bn*64*2, 256, 0, s2>>>(skip1, T1);

    /* main stream: sort + CSR chain */
    k_meta<<<Bn, 1024>>>(labels);
    k_scatter<<<NPIX/256, 256>>>(labels);
    cudaEventRecord(eSort, 0);
    k_ea<<<En/256, 256>>>(edges, ea);
    k_escan<<<1, 1024>>>();
    k_escatter<<<En/256, 256>>>(edges, ea);

    /* gathers on side streams once sort is done — persistent bounded grids so
       the active node window (and its T slice) stays L2-resident */
    cudaStreamWaitEvent(s3, eSort, 0);
    k_gather<256, 128><<<128, 256, 0, s3>>>(T2, p2);
    cudaEventRecord(eG2, s3);
    cudaStreamWaitEvent(s1, eSort, 0);
    k_gather<256, 32><<<128, 256, 0, s1>>>(T0, ph);   /* pool(proj)=h0 */
    cudaEventRecord(eG0, s1);
    cudaStreamWaitEvent(s2, eSort, 0);
    k_gather<256, 64><<<128, 256, 0, s2>>>(T1, p1);
    cudaEventRecord(eG1, s2);

    /* join: GCN chain on main stream */
    cudaStreamWaitEvent(0, eG0, 0);
    cudaStreamWaitEvent(0, eG1, 0);
    k_agg<<<Nn*32/256, 256>>>(b0, 1, lin_w);
    k_gemm_tf32<<<dim3(64, 2), 256>>>(W1);
    cudaStreamWaitEvent(0, eG2, 0);
    k_agg<<<Nn*32/256, 256>>>(b1, 2, lin_w);
    k_gemm_tf32<<<dim3(64, 2), 256>>>(W2);
    k_agg<<<Nn*32/256, 256>>>(b2, 0, lin_w);
    k_out<<<En/256, 256>>>(edges, negs, out);
}

// round 17
// speedup vs baseline: 1.2863x; 1.1891x over previous
#include <cuda_runtime.h>
#include <cuda_fp16.h>
#include <cstdint>
#include <math.h>

#define Bn    8
#define NSPn  1024
#define Hn    256
#define Wn    256
#define Nn    (Bn*NSPn)      /* 8192 superpixel nodes */
#define NPIX  (Bn*Hn*Wn)     /* 524288 pixels */
#define En    131072         /* edges */

/* ------------------------- scratch (device globals) ------------------------ */
__device__ int    g_cnt[Nn];
__device__ int    g_off[Nn];
__device__ int    g_cur[Nn];
__device__ int    g_pix[NPIX];
__device__ float  g_pc[2*Nn];
__device__ int    g_ecnt[Nn];
__device__ int    g_eoff[Nn+1];
__device__ int    g_ecur[Nn];
__device__ int    g_esrc[En];
__device__ float  g_eew[En];
__device__ __half g_P0[8192*256];                   /* proj skip0 @32x32, 4.2MB  */
__device__ __half g_S1h[(size_t)Bn*64*64*256];      /* skip1 half chan-last 16.8MB */
__device__ __half g_S2h[(size_t)Bn*128*128*256];    /* skip2 half chan-last 67MB  */
__device__ float  g_pool1[Nn*256];
__device__ float  g_pool2[Nn*256];
__device__ float  g_x[Nn*256];
__device__ float  g_h[Nn*256];
__device__ float  g_s[Nn];

/* ----- per-frame meta: hist + coord sums + scan (8 blocks, smem atomics) ---- */
__global__ __launch_bounds__(1024) void k_meta(const int* __restrict__ labels) {
    __shared__ int hist[1024];
    __shared__ int ssy[1024];
    __shared__ int ssx[1024];
    __shared__ int wsum[32];
    int b = blockIdx.x, tid = threadIdx.x;
    hist[tid] = 0; ssy[tid] = 0; ssx[tid] = 0;
    int gn = b*1024 + tid;
    g_ecnt[gn] = 0; g_ecur[gn] = 0;
    __syncthreads();
    const int* lb = labels + b*65536;
    for (int k = tid; k < 65536; k += 1024) {
        int l = lb[k];
        atomicAdd(&hist[l], 1);
        atomicAdd(&ssy[l], k >> 8);
        atomicAdd(&ssx[l], k & 255);
    }
    __syncthreads();
    int v = hist[tid];
    int lane = tid & 31, w = tid >> 5;
    int inc = v;
    #pragma unroll
    for (int d = 1; d < 32; d <<= 1) {
        int t = __shfl_up_sync(0xffffffffu, inc, d);
        if (lane >= d) inc += t;
    }
    if (lane == 31) wsum[w] = inc;
    __syncthreads();
    if (w == 0) {
        int s = wsum[lane];
        #pragma unroll
        for (int d = 1; d < 32; d <<= 1) {
            int t = __shfl_up_sync(0xffffffffu, s, d);
            if (lane >= d) s += t;
        }
        wsum[lane] = s;
    }
    __syncthreads();
    int excl = inc - v + (w ? wsum[w-1] : 0);
    int goff = b*65536 + excl;
    g_cnt[gn] = v;
    g_off[gn] = goff;
    g_cur[gn] = goff;
    float ic = 1.0f / (float)max(v, 1);
    g_pc[2*gn]   = (float)ssy[tid] * ic * (1.0f/255.0f);
    g_pc[2*gn+1] = (float)ssx[tid] * ic * (1.0f/255.0f);
}

/* full-chip counting-sort scatter */
__global__ void k_scatter(const int* __restrict__ labels) {
    int p = blockIdx.x*blockDim.x + threadIdx.x;
    if (p < NPIX) {
        int n = labels[p] + ((p >> 16) << 10);
        int pos = atomicAdd(&g_cur[n], 1);
        g_pix[pos] = p;
    }
}

/* edge weights + dst-degree count in one pass */
__global__ void k_ea(const int* __restrict__ edges, float* __restrict__ out_ea) {
    int e = blockIdx.x*blockDim.x + threadIdx.x;
    if (e < En) {
        int s = edges[e], d = edges[En + e];
        float dx = g_pc[2*s]   - g_pc[2*d];
        float dy = g_pc[2*s+1] - g_pc[2*d+1];
        out_ea[e] = expf(-(dx*dx + dy*dy) * 20.0f);   /* 1/SIGMA = 20 */
        atomicAdd(&g_ecnt[d], 1);
    }
}

/* exclusive scan of 8192 edge counts */
__global__ void k_escan() {
    __shared__ int part[1024];
    int tid = threadIdx.x;
    int base = tid * 8;
    int loc[8]; int s = 0;
    #pragma unroll
    for (int k = 0; k < 8; k++) { loc[k] = s; s += g_ecnt[base+k]; }
    part[tid] = s;
    __syncthreads();
    for (int d = 1; d < 1024; d <<= 1) {
        int v = (tid >= d) ? part[tid-d] : 0;
        __syncthreads();
        if (tid >= d) part[tid] += v;
        __syncthreads();
    }
    int pre = tid ? part[tid-1] : 0;
    #pragma unroll
    for (int k = 0; k < 8; k++) g_eoff[base+k] = pre + loc[k];
    if (tid == 1023) g_eoff[Nn] = part[1023];
}

__global__ void k_escatter(const int* __restrict__ edges, const float* __restrict__ ea) {
    int e = blockIdx.x*blockDim.x + threadIdx.x;
    if (e < En) {
        int d = edges[En + e];
        int pos = atomicAdd(&g_ecur[d], 1);
        int idx = g_eoff[d] + pos;
        g_esrc[idx] = edges[e];
        g_eew[idx]  = ea[e];
    }
}

__device__ __forceinline__ unsigned int f2tf32(float f) {
    unsigned int u;
    asm("cvt.rna.tf32.f32 %0, %1;" : "=r"(u) : "f"(f));
    return u;
}

/* ---- project skip0 @ W0 at 32x32 resolution: [8192 cells,512]@[512,256] ---- */
__global__ void k_proj0(const float* __restrict__ skip0, const float* __restrict__ Wm) {
    __shared__ float As[128][36];
    __shared__ float Bs[32][132];
    const int tid  = threadIdx.x;
    const int wid  = tid >> 5, lane = tid & 31;
    const int wm   = wid & 3, wn = wid >> 2;
    const int row_w = wm * 32;
    const int col_w = wn * 64;
    const int gid = lane >> 2, tig = lane & 3;
    const int mbase = blockIdx.x * 128;
    const int b = mbase >> 10;
    const int ijb = mbase & 1023;
    const int bn0 = blockIdx.y * 128;

    float acc[2][8][4];
    #pragma unroll
    for (int mt = 0; mt < 2; mt++)
        #pragma unroll
        for (int nt = 0; nt < 8; nt++)
            #pragma unroll
            for (int q = 0; q < 4; q++) acc[mt][nt][q] = 0.f;

    for (int k0 = 0; k0 < 512; k0 += 32) {
        #pragma unroll
        for (int i = 0; i < 4; i++) {
            int idx = tid + i*256;
            int kcol = idx >> 5, mseg = (idx & 31) * 4;
            float4 v = *(const float4*)(skip0 + ((size_t)(b*512 + k0 + kcol))*1024 + ijb + mseg);
            As[mseg  ][kcol] = __uint_as_float(f2tf32(v.x));
            As[mseg+1][kcol] = __uint_as_float(f2tf32(v.y));
            As[mseg+2][kcol] = __uint_as_float(f2tf32(v.z));
            As[mseg+3][kcol] = __uint_as_float(f2tf32(v.w));
        }
        #pragma unroll
        for (int i = 0; i < 4; i++) {
            int idx = tid + i*256;
            int kr = idx >> 5, c4 = (idx & 31) * 4;
            float4 v = *(const float4*)(Wm + (size_t)(k0+kr)*256 + bn0 + c4);
            Bs[kr][c4+0] = __uint_as_float(f2tf32(v.x));
            Bs[kr][c4+1] = __uint_as_float(f2tf32(v.y));
            Bs[kr][c4+2] = __uint_as_float(f2tf32(v.z));
            Bs[kr][c4+3] = __uint_as_float(f2tf32(v.w));
        }
        __syncthreads();
        #pragma unroll
        for (int kk = 0; kk < 32; kk += 8) {
            unsigned int af[2][4];
            #pragma unroll
            for (int mt = 0; mt < 2; mt++) {
                int r0 = row_w + mt*16 + gid;
                af[mt][0] = __float_as_uint(As[r0    ][kk + tig    ]);
                af[mt][1] = __float_as_uint(As[r0 + 8][kk + tig    ]);
                af[mt][2] = __float_as_uint(As[r0    ][kk + tig + 4]);
                af[mt][3] = __float_as_uint(As[r0 + 8][kk + tig + 4]);
            }
            #pragma unroll
            for (int nt = 0; nt < 8; nt++) {
                int n0 = col_w + nt*8 + gid;
                unsigned int b0 = __float_as_uint(Bs[kk + tig    ][n0]);
                unsigned int b1 = __float_as_uint(Bs[kk + tig + 4][n0]);
                #pragma unroll
                for (int mt = 0; mt < 2; mt++) {
                    asm volatile(
                        "mma.sync.aligned.m16n8k8.row.col.f32.tf32.tf32.f32 "
                        "{%0,%1,%2,%3}, {%4,%5,%6,%7}, {%8,%9}, {%0,%1,%2,%3};"
                        : "+f"(acc[mt][nt][0]), "+f"(acc[mt][nt][1]),
                          "+f"(acc[mt][nt][2]), "+f"(acc[mt][nt][3])
                        : "r"(af[mt][0]), "r"(af[mt][1]),
                          "r"(af[mt][2]), "r"(af[mt][3]),
                          "r"(b0), "r"(b1));
                }
            }
        }
        __syncthreads();
    }
    int grow = mbase + row_w;
    #pragma unroll
    for (int mt = 0; mt < 2; mt++) {
        #pragma unroll
        for (int nt = 0; nt < 8; nt++) {
            int r = grow + mt*16 + gid;
            int c = bn0 + col_w + nt*8 + tig*2;
            *(__half2*)(g_P0 + (size_t)r*256 + c) =
                __floats2half2_rn(acc[mt][nt][0], acc[mt][nt][1]);
            *(__half2*)(g_P0 + (size_t)(r+8)*256 + c) =
                __floats2half2_rn(acc[mt][nt][2], acc[mt][nt][3]);
        }
    }
}

/* ---- transpose-convert: chan-major fp32 [b][c][y][x] -> chan-last half ----- */
template<int C, int Hs, int Ws, int CH>
__global__ void k_conv(const float* __restrict__ f, __half* __restrict__ S) {
    __shared__ float sm[CH*(Ws+1)];
    constexpr int NCH = C / CH;
    int blk   = blockIdx.x;
    int chunk = blk % NCH;
    int by    = blk / NCH;              /* b*Hs + y */
    int b = by / Hs, y = by % Hs;
    int cbase = chunk * CH;
    const float* fb = f + ((size_t)(b*C + cbase)*Hs + y) * Ws;
    for (int t = threadIdx.x; t < CH*Ws; t += blockDim.x) {
        int c = t / Ws, j = t % Ws;
        sm[c*(Ws+1) + j] = fb[(size_t)c*Hs*Ws + j];
    }
    __syncthreads();
    __half* So = S + (size_t)by*Ws*C + cbase;
    for (int t = threadIdx.x; t < Ws*(CH/2); t += blockDim.x) {
        int x = t / (CH/2), c2 = (t % (CH/2)) * 2;
        float v0 = sm[c2*(Ws+1) + x];
        float v1 = sm[(c2+1)*(Ws+1) + x];
        *(__half2*)(So + (size_t)x*C + c2) = __floats2half2_rn(v0, v1);
    }
}

/* --- 4-tap bilinear superpixel pooling gather from native-res half source --- */
/* S layout: [((b*Hs + i)*Ws + j)*256 + c]; warp per node, lane = 8 channels.  */
template<int Hs, int Ws>
__global__ void k_gather4(const __half* __restrict__ S, float* __restrict__ pool) {
    int gw = (blockIdx.x*blockDim.x + threadIdx.x) >> 5;
    if (gw >= Nn) return;
    int lane = threadIdx.x & 31;
    int cb = lane*8;
    int off = g_off[gw], cnt = g_cnt[gw];
    int b = gw >> 10;
    const float sy = (float)(Hs-1) / 255.0f;
    const float sx = (float)(Ws-1) / 255.0f;
    float acc[8] = {};
    const __half* Sb = S + (size_t)b*Hs*Ws*256 + cb;

    for (int k = 0; k < cnt; k++) {
        int p = g_pix[off + k];
        int y = (p >> 8) & 255, x = p & 255;
        float py = (float)y * sy, px = (float)x * sx;
        int i0 = (int)py, j0 = (int)px;
        float wy = py - (float)i0, wx = px - (float)j0;
        int i1 = min(i0+1, Hs-1), j1 = min(j0+1, Ws-1);
        /* 4 independent 16B loads */
        uint4 v00 = *(const uint4*)(Sb + ((size_t)i0*Ws + j0)*256);
        uint4 v01 = *(const uint4*)(Sb + ((size_t)i0*Ws + j1)*256);
        uint4 v10 = *(const uint4*)(Sb + ((size_t)i1*Ws + j0)*256);
        uint4 v11 = *(const uint4*)(Sb + ((size_t)i1*Ws + j1)*256);
        float w00 = (1.0f-wy)*(1.0f-wx), w01 = (1.0f-wy)*wx;
        float w10 = wy*(1.0f-wx),        w11 = wy*wx;
        const __half2* h00 = (const __half2*)&v00;
        const __half2* h01 = (const __half2*)&v01;
        const __half2* h10 = (const __half2*)&v10;
        const __half2* h11 = (const __half2*)&v11;
        #pragma unroll
        for (int j = 0; j < 4; j++) {
            float2 f00 = __half22float2(h00[j]);
            float2 f01 = __half22float2(h01[j]);
            float2 f10 = __half22float2(h10[j]);
            float2 f11 = __half22float2(h11[j]);
            acc[2*j]   += w00*f00.x + w01*f01.x + w10*f10.x + w11*f11.x;
            acc[2*j+1] += w00*f00.y + w01*f01.y + w10*f10.y + w11*f11.y;
        }
    }
    float inv = 1.0f / (float)max(cnt, 1);
    float4 r0 = make_float4(acc[0]*inv, acc[1]*inv, acc[2]*inv, acc[3]*inv);
    float4 r1 = make_float4(acc[4]*inv, acc[5]*inv, acc[6]*inv, acc[7]*inv);
    *(float4*)(pool + (size_t)gw*256 + cb)     = r0;
    *(float4*)(pool + (size_t)gw*256 + cb + 4) = r1;
}

/* ------------- TF32 tensor-core GEMM: [8192,256] @ [256,256] -> g_h --------- */
__global__ void k_gemm_tf32(const float* __restrict__ Wm) {
    constexpr int K = 256;
    __shared__ float As[128][36];
    __shared__ float Bs[32][132];
    const float* A = g_x;
    const int tid  = threadIdx.x;
    const int wid  = tid >> 5, lane = tid & 31;
    const int wm   = wid & 3, wn = wid >> 2;
    const int row_w = wm * 32;
    const int col_w = wn * 64;
    const int gid = lane >> 2, tig = lane & 3;
    const float* Ab = A + (size_t)blockIdx.x * 128 * K;
    const int bn0 = blockIdx.y * 128;

    float acc[2][8][4];
    #pragma unroll
    for (int mt = 0; mt < 2; mt++)
        #pragma unroll
        for (int nt = 0; nt < 8; nt++)
            #pragma unroll
            for (int q = 0; q < 4; q++) acc[mt][nt][q] = 0.f;

    for (int k0 = 0; k0 < K; k0 += 32) {
        #pragma unroll
        for (int i = 0; i < 4; i++) {
            int idx = tid + i*256;
            int r = idx >> 3, c4 = (idx & 7) * 4;
            float4 v = *(const float4*)(Ab + (size_t)r*K + k0 + c4);
            As[r][c4+0] = __uint_as_float(f2tf32(v.x));
            As[r][c4+1] = __uint_as_float(f2tf32(v.y));
            As[r][c4+2] = __uint_as_float(f2tf32(v.z));
            As[r][c4+3] = __uint_as_float(f2tf32(v.w));
        }
        #pragma unroll
        for (int i = 0; i < 4; i++) {
            int idx = tid + i*256;
            int kr = idx >> 5, c4 = (idx & 31) * 4;
            float4 v = *(const float4*)(Wm + (size_t)(k0+kr)*256 + bn0 + c4);
            Bs[kr][c4+0] = __uint_as_float(f2tf32(v.x));
            Bs[kr][c4+1] = __uint_as_float(f2tf32(v.y));
            Bs[kr][c4+2] = __uint_as_float(f2tf32(v.z));
            Bs[kr][c4+3] = __uint_as_float(f2tf32(v.w));
        }
        __syncthreads();
        #pragma unroll
        for (int kk = 0; kk < 32; kk += 8) {
            unsigned int af[2][4];
            #pragma unroll
            for (int mt = 0; mt < 2; mt++) {
                int r0 = row_w + mt*16 + gid;
                af[mt][0] = __float_as_uint(As[r0    ][kk + tig    ]);
                af[mt][1] = __float_as_uint(As[r0 + 8][kk + tig    ]);
                af[mt][2] = __float_as_uint(As[r0    ][kk + tig + 4]);
                af[mt][3] = __float_as_uint(As[r0 + 8][kk + tig + 4]);
            }
            #pragma unroll
            for (int nt = 0; nt < 8; nt++) {
                int n0 = col_w + nt*8 + gid;
                unsigned int b0 = __float_as_uint(Bs[kk + tig    ][n0]);
                unsigned int b1 = __float_as_uint(Bs[kk + tig + 4][n0]);
                #pragma unroll
                for (int mt = 0; mt < 2; mt++) {
                    asm volatile(
                        "mma.sync.aligned.m16n8k8.row.col.f32.tf32.tf32.f32 "
                        "{%0,%1,%2,%3}, {%4,%5,%6,%7}, {%8,%9}, {%0,%1,%2,%3};"
                        : "+f"(acc[mt][nt][0]), "+f"(acc[mt][nt][1]),
                          "+f"(acc[mt][nt][2]), "+f"(acc[mt][nt][3])
                        : "r"(af[mt][0]), "r"(af[mt][1]),
                          "r"(af[mt][2]), "r"(af[mt][3]),
                          "r"(b0), "r"(b1));
                }
            }
        }
        __syncthreads();
    }
    int grow = blockIdx.x*128 + row_w;
    #pragma unroll
    for (int mt = 0; mt < 2; mt++) {
        #pragma unroll
        for (int nt = 0; nt < 8; nt++) {
            int r = grow + mt*16 + gid;
            int c = bn0 + col_w + nt*8 + tig*2;
            *(float2*)(g_h + (size_t)r*256 + c) =
                make_float2(acc[mt][nt][0], acc[mt][nt][1]);
            *(float2*)(g_h + (size_t)(r+8)*256 + c) =
                make_float2(acc[mt][nt][2], acc[mt][nt][3]);
        }
    }
}

/* ----- GCN edge aggregation + bias + relu + skip mixing (+ final s dot) ---- */
__global__ void k_agg(const float* __restrict__ bias, int mixsel,
                      const float* __restrict__ lw) {
    int gw = (blockIdx.x*blockDim.x + threadIdx.x) >> 5;
    if (gw >= Nn) return;
    int lane = threadIdx.x & 31;
    int c0 = lane*4, c1 = c0 + 128;
    int off = g_eoff[gw], cnt = g_ecnt[gw];
    float4 A0 = make_float4(0,0,0,0), A1 = make_float4(0,0,0,0);
    for (int k = 0; k < cnt; k++) {
        int s = g_esrc[off + k];
        float w = g_eew[off + k];
        const float* hr = g_h + (size_t)s*256;
        float4 v0 = *(const float4*)(hr + c0);
        float4 v1 = *(const float4*)(hr + c1);
        A0.x += w*v0.x; A0.y += w*v0.y; A0.z += w*v0.z; A0.w += w*v0.w;
        A1.x += w*v1.x; A1.y += w*v1.y; A1.z += w*v1.z; A1.w += w*v1.w;
    }
    float4 b0 = *(const float4*)(bias + c0);
    float4 b1 = *(const float4*)(bias + c1);
    float4 r0 = make_float4(fmaxf(A0.x+b0.x,0.f), fmaxf(A0.y+b0.y,0.f),
                            fmaxf(A0.z+b0.z,0.f), fmaxf(A0.w+b0.w,0.f));
    float4 r1 = make_float4(fmaxf(A1.x+b1.x,0.f), fmaxf(A1.y+b1.y,0.f),
                            fmaxf(A1.z+b1.z,0.f), fmaxf(A1.w+b1.w,0.f));
    if (mixsel) {
        const float* pool = (mixsel == 1) ? g_pool1 : g_pool2;
        float4 p0 = *(const float4*)(pool + (size_t)gw*256 + c0);
        float4 p1 = *(const float4*)(pool + (size_t)gw*256 + c1);
        r0 = make_float4(0.5f*r0.x+0.5f*p0.x, 0.5f*r0.y+0.5f*p0.y,
                         0.5f*r0.z+0.5f*p0.z, 0.5f*r0.w+0.5f*p0.w);
        r1 = make_float4(0.5f*r1.x+0.5f*p1.x, 0.5f*r1.y+0.5f*p1.y,
                         0.5f*r1.z+0.5f*p1.z, 0.5f*r1.w+0.5f*p1.w);
        *(float4*)(g_x + (size_t)gw*256 + c0) = r0;
        *(float4*)(g_x + (size_t)gw*256 + c1) = r1;
    } else {
        float4 w0 = *(const float4*)(lw + c0);
        float4 w1 = *(const float4*)(lw + c1);
        float dot = r0.x*w0.x + r0.y*w0.y + r0.z*w0.z + r0.w*w0.w
                  + r1.x*w1.x + r1.y*w1.y + r1.z*w1.z + r1.w*w1.w;
        #pragma unroll
        for (int d = 16; d; d >>= 1) dot += __shfl_down_sync(0xffffffffu, dot, d);
        if (lane == 0) g_s[gw] = dot;
    }
}

__global__ void k_out(const int* __restrict__ edges, const int* __restrict__ negs,
                      float* __restrict__ out) {
    int e = blockIdx.x*blockDim.x + threadIdx.x;
    if (e < En) {
        float ss = g_s[edges[e]];
        float sd = g_s[edges[En + e]];
        float sn = g_s[negs[e]];
        out[e]      = 1.0f / (1.0f + expf(-(ss - sn)));   /* dan */
        out[En + e] = 1.0f / (1.0f + expf(-(ss - sd)));   /* dap */
    }
}

/* ------------------------------ launcher ----------------------------------- */
extern "C" void kernel_launch(void* const* d_in, const int* in_sizes, int n_in,
                              void* d_out, int out_size) {
    const int*   labels = (const int*)  d_in[0];
    const float* skip0  = (const float*)d_in[1];
    const float* skip1  = (const float*)d_in[2];
    const float* skip2  = (const float*)d_in[3];
    const int*   edges  = (const int*)  d_in[4];
    const int*   negs   = (const int*)  d_in[5];
    const float* W0     = (const float*)d_in[6];
    const float* b0     = (const float*)d_in[7];
    const float* W1     = (const float*)d_in[8];
    const float* b1     = (const float*)d_in[9];
    const float* W2     = (const float*)d_in[10];
    const float* b2     = (const float*)d_in[11];
    const float* lin_w  = (const float*)d_in[12];
    float* out = (float*)d_out;
    float* ea  = out + 2*En;

    static bool s_init = false;
    static cudaStream_t s1, s2, s3;
    static cudaEvent_t eStart, eSort, eG0, eG1, eG2;
    if (!s_init) {
        cudaStreamCreateWithFlags(&s1, cudaStreamNonBlocking);
        cudaStreamCreateWithFlags(&s2, cudaStreamNonBlocking);
        cudaStreamCreateWithFlags(&s3, cudaStreamNonBlocking);
        cudaEventCreateWithFlags(&eStart, cudaEventDisableTiming);
        cudaEventCreateWithFlags(&eSort,  cudaEventDisableTiming);
        cudaEventCreateWithFlags(&eG0,    cudaEventDisableTiming);
        cudaEventCreateWithFlags(&eG1,    cudaEventDisableTiming);
        cudaEventCreateWithFlags(&eG2,    cudaEventDisableTiming);
        s_init = true;
    }

    __half* P0  = nullptr; cudaGetSymbolAddress((void**)&P0,  g_P0);
    __half* S1h = nullptr; cudaGetSymbolAddress((void**)&S1h, g_S1h);
    __half* S2h = nullptr; cudaGetSymbolAddress((void**)&S2h, g_S2h);
    float* p1 = nullptr; cudaGetSymbolAddress((void**)&p1, g_pool1);
    float* p2 = nullptr; cudaGetSymbolAddress((void**)&p2, g_pool2);
    float* ph = nullptr; cudaGetSymbolAddress((void**)&ph, g_h);

    /* fork side streams off the capture (default) stream */
    cudaEventRecord(eStart, 0);
    cudaStreamWaitEvent(s1, eStart, 0);
    cudaStreamWaitEvent(s2, eStart, 0);
    cudaStreamWaitEvent(s3, eStart, 0);

    /* s3: skip2 half-convert; s1: proj0 (no further expansion!); s2: skip1 */
    k_conv<256, 128, 128, 64><<<Bn*128*4, 256, 0, s3>>>(skip2, S2h);
    k_proj0<<<dim3(64, 2), 256, 0, s1>>>(skip0, W0);
    k_conv<256, 64, 64, 128><<<Bn*64*2, 256, 0, s2>>>(skip1, S1h);

    /* main stream: sort + CSR chain */
    k_meta<<<Bn, 1024>>>(labels);
    k_scatter<<<NPIX/256, 256>>>(labels);
    cudaEventRecord(eSort, 0);
    k_ea<<<En/256, 256>>>(edges, ea);
    k_escan<<<1, 1024>>>();
    k_escatter<<<En/256, 256>>>(edges, ea);

    /* 4-tap gathers directly from L2-resident native-res sources */
    cudaStreamWaitEvent(s3, eSort, 0);
    k_gather4<128, 128><<<(Nn*32)/256, 256, 0, s3>>>(S2h, p2);
    cudaEventRecord(eG2, s3);
    cudaStreamWaitEvent(s1, eSort, 0);
    k_gather4<32, 32><<<(Nn*32)/256, 256, 0, s1>>>(P0, ph);   /* pool(proj)=h0 */
    cudaEventRecord(eG0, s1);
    cudaStreamWaitEvent(s2, eSort, 0);
    k_gather4<64, 64><<<(Nn*32)/256, 256, 0, s2>>>(S1h, p1);
    cudaEventRecord(eG1, s2);

    /* join: GCN chain on main stream */
    cudaStreamWaitEvent(0, eG0, 0);
    cudaStreamWaitEvent(0, eG1, 0);
    k_agg<<<Nn*32/256, 256>>>(b0, 1, lin_w);
    k_gemm_tf32<<<dim3(64, 2), 256>>>(W1);
    cudaStreamWaitEvent(0, eG2, 0);
    k_agg<<<Nn*32/256, 256>>>(b1, 2, lin_w);
    k_gemm_tf32<<<dim3(64, 2), 256>>>(W2);
    k_agg<<<Nn*32/256, 256>>>(b2, 0, lin_w);
    k_out<<<En/256, 256>>>(edges, negs, out);
}